// round 17
// baseline (speedup 1.0000x reference)
#include <cuda_runtime.h>
#include <cuda_bf16.h>
#include <cstdint>

#define BB 32
#define HH 4
#define SS 4096
#define MM 128

typedef unsigned long long u64;

__device__ __forceinline__ u64 fma2(u64 a, u64 b, u64 c) {
    u64 d; asm("fma.rn.f32x2 %0,%1,%2,%3;" : "=l"(d) : "l"(a), "l"(b), "l"(c)); return d;
}
__device__ __forceinline__ u64 mul2(u64 a, u64 b) {
    u64 d; asm("mul.rn.f32x2 %0,%1,%2;" : "=l"(d) : "l"(a), "l"(b)); return d;
}
__device__ __forceinline__ u64 pack2(float lo, float hi) {
    u64 r; asm("mov.b64 %0,{%1,%2};" : "=l"(r) : "f"(lo), "f"(hi)); return r;
}
__device__ __forceinline__ float2 unpack2(u64 x) {
    float2 f; asm("mov.b64 {%0,%1},%2;" : "=f"(f.x), "=f"(f.y) : "l"(x)); return f;
}
__device__ __forceinline__ float hadd2(u64 x) {
    const float2 f = unpack2(x); return f.x + f.y;
}
__device__ __forceinline__ uint32_t smem_u32(const void* p) {
    return (uint32_t)__cvta_generic_to_shared(p);
}

#define CP_ASYNC16(dst, src) \
    asm volatile("cp.async.cg.shared.global [%0], [%1], 16;" :: "r"(dst), "l"(src))
#define CP_COMMIT() asm volatile("cp.async.commit_group;")
#define CP_WAIT(n)  asm volatile("cp.async.wait_group %0;" :: "n"(n))

// Scratch
__device__ float4 g_w[BB * SS];    // scaled logits (k1 -> k3)
__device__ float4 g_ps[BB * 8];    // per-tile(512-row) expsum (4 heads)

// ---------------------------------------------------------------------------
// Kernel 1: cp.async 3-stage ring of 64-row / 32KB stages, 512-row tile
// (grid 256 = one wave). TWO independent quads per warp per stage (2x ILP,
// half the barriers). Bounded logits => expsum only. Zeroes out.
// ---------------------------------------------------------------------------
#define K1_TILE 512
#define K1_STGF 8192                  // floats per stage (64 rows * 128)
#define K1_STGB 32768
#define K1_RING 3
#define K1_NSTG 8

__global__ void __launch_bounds__(256, 2) k1_dots(const float* __restrict__ mem,
                                                  const float* __restrict__ kq,
                                                  const float* __restrict__ beta,
                                                  float* __restrict__ out) {
    extern __shared__ float stg[];           // K1_RING * K1_STGF floats
    __shared__ float  scl[HH];
    __shared__ float4 ws8[8];

    const int b    = blockIdx.x >> 3;        // 8 tiles per b
    const int tile = blockIdx.x & 7;
    const int tid  = threadIdx.x;
    const int warp = tid >> 5;
    const int lane = tid & 31;
    const int l8   = lane & 7;
    const int r    = lane >> 3;

    const int srow0 = tile * K1_TILE;
    const char* gbase = (const char*)(mem + ((size_t)b * SS + srow0) * MM);
    const uint32_t sbase = smem_u32(stg);

    // prologue: issue stages 0,1
#pragma unroll
    for (int p = 0; p < 2; ++p) {
        const char* g = gbase + (size_t)p * K1_STGB + (size_t)tid * 16;
        const uint32_t d = sbase + p * K1_STGB + tid * 16;
#pragma unroll
        for (int c = 0; c < 8; ++c)
            CP_ASYNC16(d + c * 4096, g + c * 4096);
        CP_COMMIT();
    }

    // zero out (tile 0 blocks own their b)
    if (tile == 0) {
        out[b * HH * MM + tid] = 0.0f;
        out[b * HH * MM + 256 + tid] = 0.0f;
    }

    // per-head scale = beta / max(||k_h||, eps)
    if (warp < HH) {
        const float4 kv = ((const float4*)(kq + (b * HH + warp) * MM))[lane];
        float ss = kv.x * kv.x + kv.y * kv.y + kv.z * kv.z + kv.w * kv.w;
#pragma unroll
        for (int o = 16; o > 0; o >>= 1)
            ss += __shfl_xor_sync(0xFFFFFFFFu, ss, o);
        if (lane == 0)
            scl[warp] = beta[b * HH + warp] / fmaxf(sqrtf(ss), 1e-8f);
    }

    // k into registers
    ulonglong2 kk[HH][4];
#pragma unroll
    for (int h = 0; h < HH; ++h)
#pragma unroll
        for (int j = 0; j < 4; ++j)
            kk[h][j] = *(const ulonglong2*)(kq + ((b * HH + h) << 7) + j * 32 + l8 * 4);

    __syncthreads();
    const float4 sc = make_float4(scl[0], scl[1], scl[2], scl[3]);
    const float gate = (l8 == 0) ? 1.0f : 0.0f;

    float4 es = make_float4(0, 0, 0, 0);

    for (int i = 0; i < K1_NSTG; ++i) {
        CP_WAIT(1);                          // stage i ready (i+1 may be in flight)
        __syncthreads();

        // two independent quads: rows warp*8+r and warp*8+4+r of this stage
        const float* spA = stg + (i % K1_RING) * K1_STGF + (warp * 8 + r) * 128 + l8 * 4;
        const float* spB = spA + 4 * 128;

        u64 ssA = 0, dA[HH] = {0, 0, 0, 0};
        u64 ssB = 0, dB[HH] = {0, 0, 0, 0};
#pragma unroll
        for (int j = 0; j < 4; ++j) {
            const ulonglong2 vA = *(const ulonglong2*)(spA + j * 32);
            const ulonglong2 vB = *(const ulonglong2*)(spB + j * 32);
            ssA = fma2(vA.x, vA.x, ssA);
            ssB = fma2(vB.x, vB.x, ssB);
            ssA = fma2(vA.y, vA.y, ssA);
            ssB = fma2(vB.y, vB.y, ssB);
#pragma unroll
            for (int h = 0; h < HH; ++h) {
                dA[h] = fma2(vA.x, kk[h][j].x, dA[h]);
                dB[h] = fma2(vB.x, kk[h][j].x, dB[h]);
                dA[h] = fma2(vA.y, kk[h][j].y, dA[h]);
                dB[h] = fma2(vB.y, kk[h][j].y, dB[h]);
            }
        }

        float sumA = hadd2(ssA), sumB = hadd2(ssB);
        float sdA[HH], sdB[HH];
#pragma unroll
        for (int h = 0; h < HH; ++h) { sdA[h] = hadd2(dA[h]); sdB[h] = hadd2(dB[h]); }

#pragma unroll
        for (int o = 4; o > 0; o >>= 1) {
            sumA += __shfl_xor_sync(0xFFFFFFFFu, sumA, o);
            sumB += __shfl_xor_sync(0xFFFFFFFFu, sumB, o);
#pragma unroll
            for (int h = 0; h < HH; ++h) {
                sdA[h] += __shfl_xor_sync(0xFFFFFFFFu, sdA[h], o);
                sdB[h] += __shfl_xor_sync(0xFFFFFFFFu, sdB[h], o);
            }
        }

        const float rmnA = 1.0f / fmaxf(sqrtf(sumA), 1e-8f);
        const float rmnB = 1.0f / fmaxf(sqrtf(sumB), 1e-8f);
        const float4 lgA = make_float4(sdA[0] * rmnA * sc.x, sdA[1] * rmnA * sc.y,
                                       sdA[2] * rmnA * sc.z, sdA[3] * rmnA * sc.w);
        const float4 lgB = make_float4(sdB[0] * rmnB * sc.x, sdB[1] * rmnB * sc.y,
                                       sdB[2] * rmnB * sc.z, sdB[3] * rmnB * sc.w);
        const int sA = srow0 + i * 64 + warp * 8 + r;
        if (l8 == 0) {
            g_w[b * SS + sA] = lgA;
            g_w[b * SS + sA + 4] = lgB;
        }

        es.x = fmaf(gate, __expf(lgA.x) + __expf(lgB.x), es.x);
        es.y = fmaf(gate, __expf(lgA.y) + __expf(lgB.y), es.y);
        es.z = fmaf(gate, __expf(lgA.z) + __expf(lgB.z), es.z);
        es.w = fmaf(gate, __expf(lgA.w) + __expf(lgB.w), es.w);

        // issue stage i+2 (commit every iteration: uniform wait math)
        const int p = i + 2;
        if (p < K1_NSTG) {
            const char* gg = gbase + (size_t)p * K1_STGB + (size_t)tid * 16;
            const uint32_t d = sbase + (p % K1_RING) * K1_STGB + tid * 16;
#pragma unroll
            for (int c = 0; c < 8; ++c)
                CP_ASYNC16(d + c * 4096, gg + c * 4096);
        }
        CP_COMMIT();
    }

    // reduce expsum across warp, then block, then store per-tile partial
#pragma unroll
    for (int o = 16; o > 0; o >>= 1) {
        es.x += __shfl_xor_sync(0xFFFFFFFFu, es.x, o);
        es.y += __shfl_xor_sync(0xFFFFFFFFu, es.y, o);
        es.z += __shfl_xor_sync(0xFFFFFFFFu, es.z, o);
        es.w += __shfl_xor_sync(0xFFFFFFFFu, es.w, o);
    }
    if (lane == 0) ws8[warp] = es;
    __syncthreads();

    if (warp == 0) {
        float4 s = (lane < 8) ? ws8[lane] : make_float4(0, 0, 0, 0);
#pragma unroll
        for (int o = 4; o > 0; o >>= 1) {
            s.x += __shfl_xor_sync(0xFFFFFFFFu, s.x, o);
            s.y += __shfl_xor_sync(0xFFFFFFFFu, s.y, o);
            s.z += __shfl_xor_sync(0xFFFFFFFFu, s.z, o);
            s.w += __shfl_xor_sync(0xFFFFFFFFu, s.w, o);
        }
        if (lane == 0)
            g_ps[b * 8 + tile] = s;
    }
}

// ---------------------------------------------------------------------------
// Kernel 3: fused write + read with INLINE normalization (k2 deleted).
// cp.async 6-stage ring (16KB mem + 512B logits per stage). Per stage the
// warp converts its 4 rows' logits -> weights (exp * 1/S) in smem scratch.
// ---------------------------------------------------------------------------
#define K3_STRF 4224                  // floats per stage (4096 mem + 128 logits)
#define K3_WOFF 4096
#define K3_RING 6
#define K3_NSTG 16

__global__ void __launch_bounds__(256, 2) k3_write_read(const float* __restrict__ mem,
                                                        const float* __restrict__ erase,
                                                        const float* __restrict__ add,
                                                        float* __restrict__ out) {
    extern __shared__ float stg[];           // K3_RING * K3_STRF floats
    __shared__ float  acc[HH * MM];
    __shared__ float2 wscr[8 * 16];          // per-warp dup-packed weights
    __shared__ float4 sm_is;

    const int b    = blockIdx.y;
    const int tile = blockIdx.x;             // 8 tiles per b
    const int tid  = threadIdx.x;
    const int warp = tid >> 5;
    const int lane = tid & 31;

    const int srow0 = tile * 512;
    const char* gbase = (const char*)(mem + ((size_t)b * SS + srow0) * MM);
    const char* wgbase = (const char*)(&g_w[b * SS + srow0]);
    const uint32_t sbase = smem_u32(stg);

    // prologue: issue stages 0..4
#pragma unroll
    for (int p = 0; p < 5; ++p) {
        const char* g = gbase + (size_t)p * 16384 + (size_t)tid * 16;
        const uint32_t d = sbase + p * (K3_STRF * 4) + tid * 16;
#pragma unroll
        for (int c = 0; c < 4; ++c)
            CP_ASYNC16(d + c * 4096, g + c * 4096);
        if (tid < 32)
            CP_ASYNC16(sbase + p * (K3_STRF * 4) + K3_WOFF * 4 + tid * 16,
                       wgbase + (size_t)p * 512 + (size_t)tid * 16);
        CP_COMMIT();
    }

    // combine the 8 per-tile expsums -> 1/S (tiny; hidden by prologue)
    if (tid < 32) {
        float4 s4 = (tid < 8) ? g_ps[b * 8 + tid] : make_float4(0, 0, 0, 0);
#pragma unroll
        for (int o = 4; o > 0; o >>= 1) {
            s4.x += __shfl_xor_sync(0xFFFFFFFFu, s4.x, o);
            s4.y += __shfl_xor_sync(0xFFFFFFFFu, s4.y, o);
            s4.z += __shfl_xor_sync(0xFFFFFFFFu, s4.z, o);
            s4.w += __shfl_xor_sync(0xFFFFFFFFu, s4.w, o);
        }
        if (tid == 0)
            sm_is = make_float4(1.0f / s4.x, 1.0f / s4.y, 1.0f / s4.z, 1.0f / s4.w);
    }

    for (int i2 = tid; i2 < HH * MM; i2 += 256)
        acc[i2] = 0.0f;

    u64 ner2[HH][2], ar2[HH][2];
#pragma unroll
    for (int h = 0; h < HH; ++h) {
        const float4 e4 = __ldg((const float4*)(erase + (b * HH + h) * MM) + lane);
        const float4 a4 = __ldg((const float4*)(add   + (b * HH + h) * MM) + lane);
        ner2[h][0] = pack2(-e4.x, -e4.y);
        ner2[h][1] = pack2(-e4.z, -e4.w);
        ar2[h][0]  = pack2(a4.x, a4.y);
        ar2[h][1]  = pack2(a4.z, a4.w);
    }
    const u64 ones = pack2(1.0f, 1.0f);

    u64 racc[HH][2];
#pragma unroll
    for (int h = 0; h < HH; ++h) { racc[h][0] = 0; racc[h][1] = 0; }

    for (int i = 0; i < K3_NSTG; ++i) {
        CP_WAIT(4);
        __syncthreads();
        const float4 is = sm_is;

        const float* sp = stg + (i % K3_RING) * K3_STRF;

        // lanes 0..15: weight = exp(logit) * 1/S for (row warp*4+(l>>2), head l&3)
        if (lane < 16) {
            const float lv = sp[K3_WOFF + warp * 16 + lane];
            const int hh = lane & 3;
            const float isc = (hh == 0) ? is.x : (hh == 1) ? is.y
                            : (hh == 2) ? is.z : is.w;
            const float wv = __expf(lv) * isc;
            wscr[warp * 16 + lane] = make_float2(wv, wv);
        }
        __syncwarp();

#pragma unroll
        for (int q = 0; q < 4; ++q) {
            const int rl = warp * 4 + q;
            const ulonglong2 v = *(const ulonglong2*)(sp + rl * 128 + lane * 4);
            u64 w2[HH];
#pragma unroll
            for (int h = 0; h < HH; ++h)
                w2[h] = *(const u64*)&wscr[warp * 16 + q * 4 + h];

            u64 x0 = v.x, x1 = v.y;
#pragma unroll
            for (int h = 0; h < HH; ++h) {
                const u64 t0  = fma2(ner2[h][0], w2[h], ones);   // 1 - w*e
                const u64 t1  = fma2(ner2[h][1], w2[h], ones);
                const u64 wa0 = mul2(w2[h], ar2[h][0]);          // w*a
                const u64 wa1 = mul2(w2[h], ar2[h][1]);
                x0 = fma2(x0, t0, wa0);
                x1 = fma2(x1, t1, wa1);
            }
#pragma unroll
            for (int h = 0; h < HH; ++h) {
                racc[h][0] = fma2(w2[h], x0, racc[h][0]);
                racc[h][1] = fma2(w2[h], x1, racc[h][1]);
            }
        }
        __syncwarp();

        const int p = i + 5;
        if (p < K3_NSTG) {
            const char* g = gbase + (size_t)p * 16384 + (size_t)tid * 16;
            const uint32_t d = sbase + (p % K3_RING) * (K3_STRF * 4) + tid * 16;
#pragma unroll
            for (int c = 0; c < 4; ++c)
                CP_ASYNC16(d + c * 4096, g + c * 4096);
            if (tid < 32)
                CP_ASYNC16(sbase + (p % K3_RING) * (K3_STRF * 4) + K3_WOFF * 4 + tid * 16,
                           wgbase + (size_t)p * 512 + (size_t)tid * 16);
        }
        CP_COMMIT();
    }

#pragma unroll
    for (int h = 0; h < HH; ++h) {
        const float2 r0 = unpack2(racc[h][0]);
        const float2 r1 = unpack2(racc[h][1]);
        atomicAdd(&acc[h * MM + lane * 4 + 0], r0.x);
        atomicAdd(&acc[h * MM + lane * 4 + 1], r0.y);
        atomicAdd(&acc[h * MM + lane * 4 + 2], r1.x);
        atomicAdd(&acc[h * MM + lane * 4 + 3], r1.y);
    }
    __syncthreads();

    for (int i2 = tid; i2 < HH * MM; i2 += 256)
        atomicAdd(&out[b * HH * MM + i2], acc[i2]);
}

// ---------------------------------------------------------------------------
extern "C" void kernel_launch(void* const* d_in, const int* in_sizes, int n_in,
                              void* d_out, int out_size) {
    const float* mem   = (const float*)d_in[0];  // (B,S,M)
    const float* kq    = (const float*)d_in[1];  // (B,H,M)
    const float* beta  = (const float*)d_in[2];  // (B,H,1)
    const float* erase = (const float*)d_in[3];  // (B,H,M)
    const float* add   = (const float*)d_in[4];  // (B,H,M)
    float* out = (float*)d_out;                  // (B,H,M)

    (void)in_sizes; (void)n_in; (void)out_size;

    static bool attr_done = false;
    if (!attr_done) {
        cudaFuncSetAttribute(k1_dots, cudaFuncAttributeMaxDynamicSharedMemorySize,
                             K1_RING * K1_STGB);
        cudaFuncSetAttribute(k3_write_read, cudaFuncAttributeMaxDynamicSharedMemorySize,
                             K3_RING * K3_STRF * 4);
        attr_done = true;
    }

    k1_dots<<<BB * 8, 256, K1_RING * K1_STGB>>>(mem, kq, beta, out);
    k3_write_read<<<dim3(8, BB), 256, K3_RING * K3_STRF * 4>>>(mem, erase, add, out);
}